// round 14
// baseline (speedup 1.0000x reference)
#include <cuda_runtime.h>
#include <cuda_fp16.h>
#include <cstdint>
#include <math.h>

#define Bsz   8192
#define Hdim  1024
#define H2    512
#define G3    3072
#define T_PAST 60
#define T_FUT  30

// ---------------- scratch (static device globals) ----------------
__device__ float g_ec[Bsz * H2];
__device__ float g_h[2][2][Bsz * Hdim];          // fp32 hidden, [gru][pp]
__device__ __half g_ah[2][2][Bsz * Hdim];        // h as fp16, [gru][pp]
__device__ __half g_gih[2][Bsz * G3];            // gi as fp16
__device__ __half g_wh16[2][G3 * Hdim];          // wh fp16
__device__ __half g_wi16[2][G3 * H2];            // wi fp16
__device__ __half g_ec16[Bsz * H2];              // ec fp16

// ---------------- PTX helpers (sm_80-level, compute_103-safe) ----------------
__device__ __forceinline__ uint32_t smem_u32(const void* p) {
    uint32_t a;
    asm("{ .reg .u64 t; cvta.to.shared.u64 t, %1; cvt.u32.u64 %0, t; }" : "=r"(a) : "l"(p));
    return a;
}
__device__ __forceinline__ void cp16(uint32_t s, const void* g) {
    asm volatile("cp.async.cg.shared.global [%0], [%1], 16;" :: "r"(s), "l"(g));
}
__device__ __forceinline__ void cp_commit() {
    asm volatile("cp.async.commit_group;" ::: "memory");
}
template <int N> __device__ __forceinline__ void cp_wait() {
    asm volatile("cp.async.wait_group %0;" :: "n"(N) : "memory");
}
__device__ __forceinline__ void ldsm_x4(uint32_t* r, uint32_t a) {
    asm volatile("ldmatrix.sync.aligned.m8n8.x4.shared.b16 {%0,%1,%2,%3}, [%4];"
                 : "=r"(r[0]), "=r"(r[1]), "=r"(r[2]), "=r"(r[3]) : "r"(a));
}
__device__ __forceinline__ void mma_f16(float* c, const uint32_t* a, const uint32_t* b) {
    asm volatile(
        "mma.sync.aligned.m16n8k16.row.col.f32.f16.f16.f32 "
        "{%0,%1,%2,%3}, {%4,%5,%6,%7}, {%8,%9}, {%0,%1,%2,%3};"
        : "+f"(c[0]), "+f"(c[1]), "+f"(c[2]), "+f"(c[3])
        : "r"(a[0]), "r"(a[1]), "r"(a[2]), "r"(a[3]), "r"(b[0]), "r"(b[1]));
}

// ---------------- small kernels ----------------
struct F2H4 { const float* s[4]; __half* d[4]; int n[4]; };
__global__ void f2h4_kernel(F2H4 a) {
    const int stride = gridDim.x * blockDim.x;
#pragma unroll
    for (int j = 0; j < 4; j++) {
        for (int i = blockIdx.x * blockDim.x + threadIdx.x; i < a.n[j]; i += stride)
            a.d[j][i] = __float2half(a.s[j][i]);
    }
}

// ec->fp16, h0 init, output bias init — one kernel
__global__ void misc_kernel(const float* __restrict__ ctx,
                            float* __restrict__ dec, float* __restrict__ fut,
                            const float* __restrict__ fib, const float* __restrict__ fob) {
    const int stride = gridDim.x * blockDim.x;
    const int tid0 = blockIdx.x * blockDim.x + threadIdx.x;
    for (int i = tid0; i < Bsz * H2; i += stride)
        g_ec16[i] = __float2half(g_ec[i]);
    for (int i = tid0; i < Bsz * Hdim; i += stride) {
        float v = ctx[i];
        __half h = __float2half(v);
        g_h[0][0][i] = v;  g_h[1][0][i] = v;
        g_ah[0][0][i] = h; g_ah[1][0][i] = h;
    }
    for (int i = tid0; i < Bsz * T_PAST * 4; i += stride) dec[i] = fib[i & 3];
    for (int i = tid0; i < Bsz * T_FUT * 4; i += stride)  fut[i] = fob[i & 3];
}

// fp32 SIMT GEMM for ec prologue only
__global__ void gemm_bt_kernel(const float* __restrict__ A,
                               const float* __restrict__ W,
                               const float* __restrict__ bias,
                               float* __restrict__ C,
                               int N, int K, int relu) {
    __shared__ float As[16][68];
    __shared__ float Bs[16][68];
    const int t   = threadIdx.x;
    const int tx  = t & 15, ty = t >> 4;
    const int m0  = blockIdx.y << 6, n0 = blockIdx.x << 6;
    const int lrow = t >> 2;
    const int lk   = (t & 3) << 2;

    float acc[4][4] = {};
    const float* Ap = A + (size_t)(m0 + lrow) * K + lk;
    const float* Wp = W + (size_t)(n0 + lrow) * K + lk;

    for (int k0 = 0; k0 < K; k0 += 16) {
        float4 a = *(const float4*)(Ap + k0);
        float4 b = *(const float4*)(Wp + k0);
        __syncthreads();
        As[lk + 0][lrow] = a.x; As[lk + 1][lrow] = a.y;
        As[lk + 2][lrow] = a.z; As[lk + 3][lrow] = a.w;
        Bs[lk + 0][lrow] = b.x; Bs[lk + 1][lrow] = b.y;
        Bs[lk + 2][lrow] = b.z; Bs[lk + 3][lrow] = b.w;
        __syncthreads();
#pragma unroll
        for (int k = 0; k < 16; k++) {
            float4 av = *(const float4*)&As[k][ty << 2];
            float4 bv = *(const float4*)&Bs[k][tx << 2];
            float aa[4] = {av.x, av.y, av.z, av.w};
            float bb[4] = {bv.x, bv.y, bv.z, bv.w};
#pragma unroll
            for (int i = 0; i < 4; i++)
#pragma unroll
                for (int j = 0; j < 4; j++)
                    acc[i][j] += aa[i] * bb[j];
        }
    }
#pragma unroll
    for (int i = 0; i < 4; i++) {
        int m = m0 + (ty << 2) + i;
#pragma unroll
        for (int j = 0; j < 4; j++) {
            int n = n0 + (tx << 2) + j;
            float v = acc[i][j] + bias[n];
            if (relu) v = fmaxf(v, 0.0f);
            C[(size_t)m * N + n] = v;
        }
    }
}

// ---------------- fp16 HMMA 3-gate GEMM, M=128 tile, 512 thr ----------------
static constexpr int OFF_W    = 128 * 48;                // 6144
static constexpr int STAGE    = OFF_W + 192 * 48;        // 15360
static constexpr int NS       = 8;
static constexpr int DYN_SMEM = NS * STAGE;              // 122880

struct GemmArgs {
    const __half *a16, *w16;
    const float* bias;         // [3*1024]
    const __half* gi;          // MODE 0
    const float* hin;          // MODE 0
    float*       hout;         // MODE 0
    __half*      oh;           // MODE 0
    __half*      giout;        // MODE 1
    const float* pw;           // MODE 0: proj weight [4,1024]
    float*       pout;         // MODE 0: out + t*4
    int          pstride;      // MODE 0: T*4
    int          prelu;        // MODE 0
    int          lda;          // row stride (elems) of A and W
};

// MODE 0: fused GRU step + proj (K16=64).  MODE 1: gi GEMM + bias -> fp16 (K16=32)
// Grouped pipeline: 2 k16-stages per barrier, prefetch 3 groups ahead.
template <int MODE, int K16>
__global__ void __launch_bounds__(512, 1)
hmma1_kernel(GemmArgs arg0, GemmArgs arg1) {
    extern __shared__ char dsmem[];
    __shared__ float s_bh[192];
    __shared__ float s_pw[256];

    const GemmArgs& A = (blockIdx.z == 0) ? arg0 : arg1;

    const int t   = threadIdx.x;
    const int wid = t >> 5, L = t & 31;
    const int n0  = blockIdx.x * 64;     // per-gate column tile
    const int m0  = blockIdx.y * 128;    // batch tile
    const int mwarp = wid >> 2, nwarp = wid & 3;   // 4 x 4
    const int lda = A.lda;

    const uint32_t dynb = smem_u32(dsmem);

    if (t < 192) s_bh[t] = A.bias[(t >> 6) * 1024 + n0 + (t & 63)];
    if (MODE == 0 && t >= 256 && t < 512)
        s_pw[t - 256] = A.pw[((t - 256) >> 6) * 1024 + n0 + ((t - 256) & 63)];

    // ---- cp.async chunk assignment: 640 x 16B chunks per stage ----
    const __half* src0;
    uint32_t dst0;
    {
        int c = t;
        if (c < 256) {
            int row = c >> 1, half = c & 1;
            src0 = A.a16 + (size_t)(m0 + row) * lda + 8 * half;
            dst0 = (uint32_t)(row * 48 + half * 16);
        } else {
            int cw = c - 256;
            int row = cw >> 1, half = cw & 1;
            int g = row >> 6, n = row & 63;
            src0 = A.w16 + (size_t)(g * 1024 + n0 + n) * lda + 8 * half;
            dst0 = (uint32_t)(OFF_W + row * 48 + half * 16);
        }
    }
    const __half* src1 = nullptr;
    uint32_t dst1 = 0;
    if (t < 128) {
        int cw = (512 + t) - 256;   // 256..383
        int row = cw >> 1, half = cw & 1;
        int g = row >> 6, n = row & 63;
        src1 = A.w16 + (size_t)(g * 1024 + n0 + n) * lda + 8 * half;
        dst1 = (uint32_t)(OFF_W + row * 48 + half * 16);
    }

    auto load_stage = [&](uint32_t base, int ke) {
        cp16(base + dst0, src0 + ke);
        if (t < 128) cp16(base + dst1, src1 + ke);
    };

    // ---- ldmatrix lane offsets ----
    const uint32_t aoff = (uint32_t)((mwarp * 32 + (L & 15)) * 48 + (L >> 4) * 16);
    uint32_t boff[3];
    {
        int nlane = (L & 7) + ((L & 16) ? 8 : 0);
        int k8 = (L >> 3) & 1;
#pragma unroll
        for (int g = 0; g < 3; g++)
            boff[g] = (uint32_t)(OFF_W + (g * 64 + nwarp * 16 + nlane) * 48 + k8 * 16);
    }

    // ---- pipeline prologue: preload groups 0..2 (stages 0..5), commit per pair ----
#pragma unroll
    for (int s = 0; s < 6; s++) {
        load_stage(dynb + s * STAGE, s * 16);
        if (s & 1) cp_commit();
    }

    float acc[3][2][2][4];   // [gate][m16][n8][4]
#pragma unroll
    for (int g = 0; g < 3; g++)
#pragma unroll
        for (int mt = 0; mt < 2; mt++)
#pragma unroll
            for (int nt = 0; nt < 2; nt++)
#pragma unroll
                for (int e = 0; e < 4; e++) acc[g][mt][nt][e] = 0.0f;

    // ---- main K loop: one barrier per 2 k16-stages ----
#pragma unroll 1
    for (int p = 0; p < K16 / 2; p++) {
        cp_wait<2>();
        __syncthreads();
#pragma unroll
        for (int j = 0; j < 2; j++) {
            const int ki = 2 * p + j;
            const uint32_t sb = dynb + (uint32_t)(ki & (NS - 1)) * STAGE;

            uint32_t A0[4], A1[4];
            ldsm_x4(A0, sb + aoff);
            ldsm_x4(A1, sb + aoff + 16 * 48);
#pragma unroll
            for (int g = 0; g < 3; g++) {
                uint32_t B[4];
                ldsm_x4(B, sb + boff[g]);
                mma_f16(acc[g][0][0], A0, &B[0]);
                mma_f16(acc[g][0][1], A0, &B[2]);
                mma_f16(acc[g][1][0], A1, &B[0]);
                mma_f16(acc[g][1][1], A1, &B[2]);
            }
        }
        // prefetch group p+3 (stages 2p+6, 2p+7) into the pair consumed in group p-1
        const int kn = 2 * p + 6;
        if (kn < K16) {
            load_stage(dynb + (uint32_t)(kn & (NS - 1)) * STAGE, kn * 16);
            load_stage(dynb + (uint32_t)((kn + 1) & (NS - 1)) * STAGE, (kn + 1) * 16);
        }
        cp_commit();
    }

    // ---- epilogue ----
    const int rq = L >> 2, cq = L & 3;
#pragma unroll
    for (int mt = 0; mt < 2; mt++) {
#pragma unroll
        for (int rs = 0; rs < 2; rs++) {
            const int row = m0 + mwarp * 32 + mt * 16 + rs * 8 + rq;
            if (MODE == 1) {
                __half* go = A.giout + (size_t)row * G3;
#pragma unroll
                for (int g = 0; g < 3; g++)
#pragma unroll
                    for (int nt = 0; nt < 2; nt++) {
                        const int c = nwarp * 16 + nt * 8 + 2 * cq;
                        float v0 = acc[g][mt][nt][rs * 2 + 0] + s_bh[g * 64 + c];
                        float v1 = acc[g][mt][nt][rs * 2 + 1] + s_bh[g * 64 + c + 1];
                        *(__half2*)(go + g * 1024 + n0 + c) = __floats2half2_rn(v0, v1);
                    }
            } else {
                const __half* gib = A.gi + (size_t)row * G3;
                const float* hinr = A.hin + (size_t)row * Hdim;
                float*       hor  = A.hout + (size_t)row * Hdim;
                __half*      hhr  = A.oh  + (size_t)row * Hdim;
                float pacc[4] = {0.f, 0.f, 0.f, 0.f};
#pragma unroll
                for (int nt = 0; nt < 2; nt++) {
                    const int c   = nwarp * 16 + nt * 8 + 2 * cq;
                    const int col = n0 + c;
                    float2 ir  = __half22float2(*(const __half2*)(gib + col));
                    float2 iz  = __half22float2(*(const __half2*)(gib + 1024 + col));
                    float2 inn = __half22float2(*(const __half2*)(gib + 2048 + col));
                    float2 hv  = *(const float2*)(hinr + col);
                    float ira[2] = {ir.x, ir.y};
                    float iza[2] = {iz.x, iz.y};
                    float ina[2] = {inn.x, inn.y};
                    float hva[2] = {hv.x, hv.y};
                    float o[2];
#pragma unroll
                    for (int e = 0; e < 2; e++) {
                        float hr = acc[0][mt][nt][rs * 2 + e] + s_bh[c + e];
                        float hz = acc[1][mt][nt][rs * 2 + e] + s_bh[64 + c + e];
                        float hn = acc[2][mt][nt][rs * 2 + e] + s_bh[128 + c + e];
                        float r = 1.0f / (1.0f + __expf(-(ira[e] + hr)));
                        float z = 1.0f / (1.0f + __expf(-(iza[e] + hz)));
                        float ex = __expf(2.0f * (ina[e] + r * hn));
                        float nn = 1.0f - 2.0f / (ex + 1.0f);
                        o[e] = (1.0f - z) * nn + z * hva[e];
                    }
                    *(float2*)(hor + col) = make_float2(o[0], o[1]);
                    *(__half2*)(hhr + col) = __half2(__float2half(o[0]), __float2half(o[1]));
                    float p0 = A.prelu ? fmaxf(o[0], 0.0f) : o[0];
                    float p1 = A.prelu ? fmaxf(o[1], 0.0f) : o[1];
#pragma unroll
                    for (int i = 0; i < 4; i++)
                        pacc[i] += p0 * s_pw[i * 64 + c] + p1 * s_pw[i * 64 + c + 1];
                }
#pragma unroll
                for (int i = 0; i < 4; i++) {
                    float v = pacc[i];
                    v += __shfl_xor_sync(0xffffffffu, v, 1);
                    v += __shfl_xor_sync(0xffffffffu, v, 2);
                    if (cq == 0)
                        atomicAdd(A.pout + (size_t)row * A.pstride + i, v);
                }
            }
        }
    }
}

// ---------------------------------------------------------------------------
extern "C" void kernel_launch(void* const* d_in, const int* in_sizes, int n_in,
                              void* d_out, int out_size) {
    const float* context = (const float*)d_in[0];
    const float* wc      = (const float*)d_in[1];
    const float* bc      = (const float*)d_in[2];
    const float* g1wi    = (const float*)d_in[3];
    const float* g1wh    = (const float*)d_in[4];
    const float* g1bi    = (const float*)d_in[5];
    const float* g1bh    = (const float*)d_in[6];
    const float* g2wi    = (const float*)d_in[7];
    const float* g2wh    = (const float*)d_in[8];
    const float* g2bi    = (const float*)d_in[9];
    const float* g2bh    = (const float*)d_in[10];
    const float* fiw     = (const float*)d_in[11];
    const float* fib     = (const float*)d_in[12];
    const float* fow     = (const float*)d_in[13];
    const float* fob     = (const float*)d_in[14];

    float* dec = (float*)d_out;
    float* fut = (float*)d_out + (size_t)Bsz * T_PAST * 4;

    float *ec_p, *h_p;
    __half *ah_p, *gih_p, *wh16_p, *wi16_p, *ec16_p;
    cudaGetSymbolAddress((void**)&ec_p,   g_ec);
    cudaGetSymbolAddress((void**)&h_p,    g_h);
    cudaGetSymbolAddress((void**)&ah_p,   g_ah);
    cudaGetSymbolAddress((void**)&gih_p,  g_gih);
    cudaGetSymbolAddress((void**)&wh16_p, g_wh16);
    cudaGetSymbolAddress((void**)&wi16_p, g_wi16);
    cudaGetSymbolAddress((void**)&ec16_p, g_ec16);

    const size_t HN  = (size_t)Bsz * Hdim;
    const size_t WN  = (size_t)G3 * Hdim;
    const size_t WIN = (size_t)G3 * H2;
    const size_t GN  = (size_t)Bsz * G3;
    auto Hf = [&](int g, int p) { return h_p  + ((size_t)g * 2 + p) * HN; };
    auto Hh = [&](int g, int p) { return ah_p + ((size_t)g * 2 + p) * HN; };

    cudaFuncSetAttribute(hmma1_kernel<0, 64>, cudaFuncAttributeMaxDynamicSharedMemorySize, DYN_SMEM);
    cudaFuncSetAttribute(hmma1_kernel<1, 32>, cudaFuncAttributeMaxDynamicSharedMemorySize, DYN_SMEM);

    // ---- prologue (our #4 = hmma MODE-1 GEMM, the ncu capture target) ----
    {   // 1: all weight conversions
        F2H4 a;
        a.s[0] = g1wh; a.d[0] = wh16_p;       a.n[0] = (int)WN;
        a.s[1] = g2wh; a.d[1] = wh16_p + WN;  a.n[1] = (int)WN;
        a.s[2] = g1wi; a.d[2] = wi16_p;       a.n[2] = (int)WIN;
        a.s[3] = g2wi; a.d[3] = wi16_p + WIN; a.n[3] = (int)WIN;
        f2h4_kernel<<<2048, 256>>>(a);
    }
    // 2: ec = relu(context @ wc^T + bc)
    gemm_bt_kernel<<<dim3(H2 / 64, Bsz / 64), 256>>>(context, wc, bc, ec_p, H2, Hdim, 1);
    // 3: ec->fp16, h0 init, out bias init
    misc_kernel<<<2048, 256>>>(context, dec, fut, fib, fob);
    // 4: gi = ec @ wi^T + bi (fp16 out, both GRUs)
    {
        GemmArgs a0 = {}, a1 = {};
        a0.a16 = ec16_p; a0.w16 = wi16_p; a0.bias = g1bi; a0.giout = gih_p; a0.lda = H2;
        a1 = a0;
        a1.w16 = wi16_p + WIN; a1.bias = g2bi; a1.giout = gih_p + GN;
        hmma1_kernel<1, 32><<<dim3(16, Bsz / 128, 2), 512, DYN_SMEM>>>(a0, a1);
    }

    // ---- recurrent steps (proj fused) ----
    for (int t = 0; t < T_PAST; t++) {
        const int cur = t & 1;
        GemmArgs a0 = {}, a1 = {};
        a0.a16 = Hh(0, cur); a0.w16 = wh16_p; a0.bias = g1bh;
        a0.gi = gih_p; a0.hin = Hf(0, cur); a0.hout = Hf(0, cur ^ 1);
        a0.oh = Hh(0, cur ^ 1); a0.lda = Hdim;
        a0.pw = fiw; a0.pout = dec + (size_t)t * 4; a0.pstride = T_PAST * 4; a0.prelu = 0;
        const int z = (t < T_FUT) ? 2 : 1;
        if (t < T_FUT) {
            a1.a16 = Hh(1, cur); a1.w16 = wh16_p + WN; a1.bias = g2bh;
            a1.gi = gih_p + GN; a1.hin = Hf(1, cur); a1.hout = Hf(1, cur ^ 1);
            a1.oh = Hh(1, cur ^ 1); a1.lda = Hdim;
            a1.pw = fow; a1.pout = fut + (size_t)t * 4; a1.pstride = T_FUT * 4; a1.prelu = 1;
        }
        hmma1_kernel<0, 64><<<dim3(16, Bsz / 128, z), 512, DYN_SMEM>>>(a0, a1);
    }
}